// round 6
// baseline (speedup 1.0000x reference)
#include <cuda_runtime.h>
#include <math.h>
#include <stdint.h>

// PointLoss_like_GPS — GB300 sm_103a, Round 6
// Algorithmic: x-bucketed nearest-neighbor with exact window pruning.
// Kernel A: bucket-sort all 8 point sets by x (64 bins, exact fp32 edges).
// Kernel B: warp-autonomous windowed NN search over sorted queries + fused
//           epilogue + ticketed last-block reduction.

#define NPTS    4096
#define DIMS    3
#define THREADS 256
#define NBUCK   64
#define XMIN    (-3.0f)
#define BW      (6.0f / NBUCK)       /* 0.09375 = 3/32, exact in fp32 */
#define MAXSETS 8                    /* 2B at B=4 */

__device__ float4       g_pts[MAXSETS][NPTS];      // bucket-sorted (x,y,z,0)
__device__ int          g_bstart[MAXSETS][NBUCK + 1];
__device__ float        g_partials[256];
__device__ unsigned int g_ticket;

__device__ __forceinline__ int bucket_of(float x)
{
    int b = (int)floorf((x - XMIN) * (1.0f / BW));
    return min(max(b, 0), NBUCK - 1);
}

// ---------------- Kernel A: histogram + prefix + scatter (one block/set) ----
__global__ void __launch_bounds__(THREADS)
bucket_kernel(const float* __restrict__ a1, const float* __restrict__ a2)
{
    __shared__ int hist[NBUCK];
    __shared__ int start[NBUCK + 1];
    __shared__ int cur[NBUCK];

    const int s   = blockIdx.x;            // set: 2b = array1[b], 2b+1 = array2[b]
    const int tid = threadIdx.x;
    if (s == 0 && tid == 0) g_ticket = 0;  // reset for kernel B's tail

    const int bb = s >> 1;
    const float* base = ((s & 1) ? a2 : a1) + (size_t)bb * NPTS * DIMS;

    if (tid < NBUCK) hist[tid] = 0;
    __syncthreads();

    for (int i = tid; i < NPTS; i += THREADS)
        atomicAdd(&hist[bucket_of(base[i * 3])], 1);
    __syncthreads();

    if (tid == 0) {
        int acc = 0;
        for (int k = 0; k < NBUCK; k++) { start[k] = acc; cur[k] = acc; acc += hist[k]; }
        start[NBUCK] = acc;
    }
    __syncthreads();

    if (tid <= NBUCK) g_bstart[s][tid] = start[tid];

    for (int i = tid; i < NPTS; i += THREADS) {
        const float x = base[i * 3 + 0];
        const float y = base[i * 3 + 1];
        const float z = base[i * 3 + 2];
        const int pos = atomicAdd(&cur[bucket_of(x)], 1);
        g_pts[s][pos] = make_float4(x, y, z, 0.0f);
    }
}

// ---------------- Kernel B: windowed NN search + fused reduction ------------
__global__ void __launch_bounds__(THREADS)
search_kernel(const float* __restrict__ alpha_p,
              const float* __restrict__ beta_p,
              float* __restrict__ out,
              int nblocks, float scale)
{
    __shared__ int   sbs[NBUCK + 1];
    __shared__ float red[THREADS / 32];

    const int tid   = threadIdx.x;
    const int bx    = blockIdx.x;
    const int chunk = bx & 15;             // 16 chunks of 256 queries
    const int p     = bx >> 4;             // pair [0, 2B)
    const int bb    = p >> 1;
    // p even: f12 -> samples=array2[b] (set 2b+1), refs=array1[b] (set 2b)
    const int sset  = (p & 1) ? (2 * bb) : (2 * bb + 1);
    const int rset  = sset ^ 1;

    if (tid <= NBUCK) sbs[tid] = g_bstart[rset][tid];
    __syncthreads();

    const int q = chunk * THREADS + tid;   // sorted-order query index
    const float4 qp = g_pts[sset][q];
    const float qx = qp.x, qy = qp.y, qz = qp.z;

    // warp window: buckets of first/last query in this warp (sorted order)
    const int myb = bucket_of(qx);
    int blo = __shfl_sync(0xffffffffu, myb, 0);
    int bhi = __shfl_sync(0xffffffffu, myb, 31);

    const float4* __restrict__ R = g_pts[rset];
    float dmin = 3.402823466e38f;

    // initial scan: the warp's own bucket span
    for (int j = sbs[blo]; j < sbs[bhi + 1]; ++j) {
        const float4 r = R[j];
        const float d = fabsf(qx - r.x) + fabsf(qy - r.y) + fabsf(qz - r.z);
        dmin = fminf(dmin, d);
    }

    // expand window until every lane's dmin is provably final.
    // Unscanned refs on the left have x < XMIN + blo*BW (exact edge), so their
    // L1 distance >= qx - edge; safe to stop when dmin <= that bound.
    while (true) {
        const bool lok = (blo == 0) ||
                         (dmin <= qx - (XMIN + (float)blo * BW));
        const bool rok = (bhi == NBUCK - 1) ||
                         (dmin <= (XMIN + (float)(bhi + 1) * BW) - qx);
        if (__all_sync(0xffffffffu, lok && rok)) break;

        const int nlo = max(blo - 1, 0);
        const int nhi = min(bhi + 1, NBUCK - 1);
        if (nlo == blo && nhi == bhi) break;   // full coverage

        for (int j = sbs[nlo]; j < sbs[blo]; ++j) {
            const float4 r = R[j];
            const float d = fabsf(qx - r.x) + fabsf(qy - r.y) + fabsf(qz - r.z);
            dmin = fminf(dmin, d);
        }
        for (int j = sbs[bhi + 1]; j < sbs[nhi + 1]; ++j) {
            const float4 r = R[j];
            const float d = fabsf(qx - r.x) + fabsf(qy - r.y) + fabsf(qz - r.z);
            dmin = fminf(dmin, d);
        }
        blo = nlo; bhi = nhi;
    }

    // fused epilogue
    const float alpha = *alpha_p;
    const float beta  = *beta_p;
    const float delta = __powf(alpha, -1.0f / beta);
    const float sv = alpha * __powf(dmin, beta) + delta;
    float v = -sv * __expf(-sv);

    #pragma unroll
    for (int o = 16; o > 0; o >>= 1)
        v += __shfl_down_sync(0xffffffffu, v, o);
    if ((tid & 31) == 0) red[tid >> 5] = v;
    __syncthreads();

    if (tid == 0) {
        float bsum = 0.0f;
        #pragma unroll
        for (int w = 0; w < THREADS / 32; w++) bsum += red[w];
        g_partials[bx] = bsum;
        __threadfence();
        const unsigned int t = atomicAdd(&g_ticket, 1u);
        if (t == (unsigned)(nblocks - 1)) {
            float total = 0.0f;
            for (int r = 0; r < nblocks; r++)
                total += *((volatile float*)&g_partials[r]);
            out[0] = total * scale;
        }
    }
}

extern "C" void kernel_launch(void* const* d_in, const int* in_sizes, int n_in,
                              void* d_out, int out_size)
{
    const float* a1    = (const float*)d_in[0];
    const float* a2    = (const float*)d_in[1];
    const float* alpha = (const float*)d_in[2];
    const float* beta  = (const float*)d_in[3];
    float* out = (float*)d_out;

    const int B = in_sizes[0] / (NPTS * DIMS);
    const int nsets    = 2 * B;                 // 8 at B=4
    const int nblocksB = 2 * B * 16;            // 128 at B=4
    const float scale  = 50.0f / (float)B;

    bucket_kernel<<<nsets, THREADS>>>(a1, a2);
    search_kernel<<<nblocksB, THREADS>>>(alpha, beta, out, nblocksB, scale);
}

// round 7
// speedup vs baseline: 3.5176x; 3.5176x over previous
#include <cuda_runtime.h>
#include <math.h>
#include <stdint.h>

// PointLoss_like_GPS — GB300 sm_103a, Round 7
// x-bucket pruning (R6, exact) + shared-memory f32x2 scan engine (R5).
// Kernel A: bucket-sort sets into sorted SoA global arrays.
// Kernel B: copy full sorted ref set to shared SoA; warp-uniform windowed
//           scan with exact-edge termination; fused ticketed reduction.

#define NPTS     4096
#define DIMS     3
#define THREADS  256
#define ATHREADS 512
#define NBUCK    64
#define XMIN     (-3.0f)
#define BW       (6.0f / NBUCK)      /* 3/32, exact in fp32; k*BW exact for k<=64 */
#define MAXSETS  8                   /* 2B at B=4 */

__device__ float        g_sx[MAXSETS][NPTS];   // bucket-sorted SoA
__device__ float        g_sy[MAXSETS][NPTS];
__device__ float        g_sz[MAXSETS][NPTS];
__device__ int          g_bstart[MAXSETS][NBUCK + 1];
__device__ float        g_partials[256];
__device__ unsigned int g_ticket;

__device__ __forceinline__ int bucket_of(float x)
{
    int b = (int)floorf((x - XMIN) * (1.0f / BW));
    return min(max(b, 0), NBUCK - 1);
}

__device__ __forceinline__ float2 addf32x2(unsigned long long a, unsigned long long b)
{
    float2 r;
    asm("{\n\t"
        ".reg .b64 t;\n\t"
        "add.rn.f32x2 t, %2, %3;\n\t"
        "mov.b64 {%0, %1}, t;\n\t"
        "}"
        : "=f"(r.x), "=f"(r.y) : "l"(a), "l"(b));
    return r;
}

__device__ __forceinline__ unsigned long long bcast2(float v)
{
    unsigned long long r;
    asm("mov.b64 %0, {%1, %1};" : "=l"(r) : "f"(v));
    return r;
}

// scan candidates [a, b) from shared SoA (4-group aligned; extra points are
// idempotent for the running min)
__device__ __forceinline__ void scan_range(
    const float* shX, const float* shY, const float* shZ,
    int a, int b,
    unsigned long long nqx2, unsigned long long nqy2, unsigned long long nqz2,
    float& dm0, float& dm1, float& dm2, float& dm3)
{
    const double2* X = (const double2*)shX;
    const double2* Y = (const double2*)shY;
    const double2* Z = (const double2*)shZ;
    const int g0 = a >> 2;
    const int g1 = (b + 3) >> 2;

    #pragma unroll 2
    for (int g = g0; g < g1; ++g) {
        const double2 xv = X[g], yv = Y[g], zv = Z[g];

        const float2 dx01 = addf32x2(__double_as_longlong(xv.x), nqx2);
        const float2 dx23 = addf32x2(__double_as_longlong(xv.y), nqx2);
        const float2 dy01 = addf32x2(__double_as_longlong(yv.x), nqy2);
        const float2 dy23 = addf32x2(__double_as_longlong(yv.y), nqy2);
        const float2 dz01 = addf32x2(__double_as_longlong(zv.x), nqz2);
        const float2 dz23 = addf32x2(__double_as_longlong(zv.y), nqz2);

        const float s0 = (fabsf(dx01.x) + fabsf(dy01.x)) + fabsf(dz01.x);
        const float s1 = (fabsf(dx01.y) + fabsf(dy01.y)) + fabsf(dz01.y);
        const float s2 = (fabsf(dx23.x) + fabsf(dy23.x)) + fabsf(dz23.x);
        const float s3 = (fabsf(dx23.y) + fabsf(dy23.y)) + fabsf(dz23.y);

        dm0 = fminf(dm0, s0);
        dm1 = fminf(dm1, s1);
        dm2 = fminf(dm2, s2);
        dm3 = fminf(dm3, s3);
    }
}

// ---------------- Kernel A: bucket sort into SoA ----------------------------
__global__ void __launch_bounds__(ATHREADS)
bucket_kernel(const float* __restrict__ a1, const float* __restrict__ a2)
{
    __shared__ int hist[NBUCK];
    __shared__ int start[NBUCK + 1];
    __shared__ int cur[NBUCK];

    const int s   = blockIdx.x;
    const int tid = threadIdx.x;
    if (s == 0 && tid == 0) g_ticket = 0;

    const int bb = s >> 1;
    const float* base = ((s & 1) ? a2 : a1) + (size_t)bb * NPTS * DIMS;

    if (tid < NBUCK) hist[tid] = 0;
    __syncthreads();

    for (int i = tid; i < NPTS; i += ATHREADS)
        atomicAdd(&hist[bucket_of(base[i * 3])], 1);
    __syncthreads();

    if (tid == 0) {
        int acc = 0;
        for (int k = 0; k < NBUCK; k++) { start[k] = acc; cur[k] = acc; acc += hist[k]; }
        start[NBUCK] = acc;
    }
    __syncthreads();

    if (tid <= NBUCK) g_bstart[s][tid] = start[tid];

    for (int i = tid; i < NPTS; i += ATHREADS) {
        const float x = base[i * 3 + 0];
        const float y = base[i * 3 + 1];
        const float z = base[i * 3 + 2];
        const int pos = atomicAdd(&cur[bucket_of(x)], 1);
        g_sx[s][pos] = x;
        g_sy[s][pos] = y;
        g_sz[s][pos] = z;
    }
}

// ---------------- Kernel B: shared windowed NN + fused reduction ------------
__global__ void __launch_bounds__(THREADS)
search_kernel(const float* __restrict__ alpha_p,
              const float* __restrict__ beta_p,
              float* __restrict__ out,
              int nblocks, float scale)
{
    __shared__ __align__(16) float shX[NPTS];
    __shared__ __align__(16) float shY[NPTS];
    __shared__ __align__(16) float shZ[NPTS];
    __shared__ int   sbs[NBUCK + 1];
    __shared__ float red[THREADS / 32];

    const int tid   = threadIdx.x;
    const int bx    = blockIdx.x;
    const int chunk = bx & 15;
    const int p     = bx >> 4;
    const int bb    = p >> 1;
    const int sset  = (p & 1) ? (2 * bb) : (2 * bb + 1);
    const int rset  = sset ^ 1;

    if (tid <= NBUCK) sbs[tid] = g_bstart[rset][tid];

    // full sorted ref set -> shared SoA (float4 copies, 4 iters each array)
    {
        const float4* gx = (const float4*)g_sx[rset];
        const float4* gy = (const float4*)g_sy[rset];
        const float4* gz = (const float4*)g_sz[rset];
        float4* dx = (float4*)shX;
        float4* dy = (float4*)shY;
        float4* dz = (float4*)shZ;
        #pragma unroll
        for (int i = 0; i < NPTS / 4 / THREADS; i++) {
            dx[tid + i * THREADS] = gx[tid + i * THREADS];
            dy[tid + i * THREADS] = gy[tid + i * THREADS];
            dz[tid + i * THREADS] = gz[tid + i * THREADS];
        }
    }
    __syncthreads();

    const int q = chunk * THREADS + tid;           // sorted-order query index
    const float qx = g_sx[sset][q];
    const float qy = g_sy[sset][q];
    const float qz = g_sz[sset][q];

    const unsigned long long nqx2 = bcast2(-qx);
    const unsigned long long nqy2 = bcast2(-qy);
    const unsigned long long nqz2 = bcast2(-qz);

    const int myb = bucket_of(qx);
    int blo = __shfl_sync(0xffffffffu, myb, 0);
    int bhi = __shfl_sync(0xffffffffu, myb, 31);

    float dm0 = 3.402823466e38f, dm1 = dm0, dm2 = dm0, dm3 = dm0;

    // initial scan: warp's own bucket span
    scan_range(shX, shY, shZ, sbs[blo], sbs[bhi + 1],
               nqx2, nqy2, nqz2, dm0, dm1, dm2, dm3);

    // expand until every lane's dmin is provably final (exact fp32 edges)
    while (true) {
        const float dcur = fminf(fminf(dm0, dm1), fminf(dm2, dm3));
        const bool lok = (blo == 0) ||
                         (dcur <= qx - (XMIN + (float)blo * BW));
        const bool rok = (bhi == NBUCK - 1) ||
                         (dcur <= (XMIN + (float)(bhi + 1) * BW) - qx);
        if (__all_sync(0xffffffffu, lok && rok)) break;

        const int nlo = max(blo - 1, 0);
        const int nhi = min(bhi + 1, NBUCK - 1);
        if (nlo == blo && nhi == bhi) break;       // full coverage

        if (nlo < blo)
            scan_range(shX, shY, shZ, sbs[nlo], sbs[blo],
                       nqx2, nqy2, nqz2, dm0, dm1, dm2, dm3);
        if (nhi > bhi)
            scan_range(shX, shY, shZ, sbs[bhi + 1], sbs[nhi + 1],
                       nqx2, nqy2, nqz2, dm0, dm1, dm2, dm3);
        blo = nlo; bhi = nhi;
    }

    const float dmin = fminf(fminf(dm0, dm1), fminf(dm2, dm3));

    const float alpha = *alpha_p;
    const float beta  = *beta_p;
    const float delta = __powf(alpha, -1.0f / beta);
    const float sv = alpha * __powf(dmin, beta) + delta;
    float v = -sv * __expf(-sv);

    #pragma unroll
    for (int o = 16; o > 0; o >>= 1)
        v += __shfl_down_sync(0xffffffffu, v, o);
    if ((tid & 31) == 0) red[tid >> 5] = v;
    __syncthreads();

    if (tid == 0) {
        float bsum = 0.0f;
        #pragma unroll
        for (int w = 0; w < THREADS / 32; w++) bsum += red[w];
        g_partials[bx] = bsum;
        __threadfence();
        const unsigned int t = atomicAdd(&g_ticket, 1u);
        if (t == (unsigned)(nblocks - 1)) {
            float total = 0.0f;
            for (int r = 0; r < nblocks; r++)
                total += *((volatile float*)&g_partials[r]);
            out[0] = total * scale;
        }
    }
}

extern "C" void kernel_launch(void* const* d_in, const int* in_sizes, int n_in,
                              void* d_out, int out_size)
{
    const float* a1    = (const float*)d_in[0];
    const float* a2    = (const float*)d_in[1];
    const float* alpha = (const float*)d_in[2];
    const float* beta  = (const float*)d_in[3];
    float* out = (float*)d_out;

    const int B = in_sizes[0] / (NPTS * DIMS);
    const int nsets    = 2 * B;
    const int nblocksB = 2 * B * 16;
    const float scale  = 50.0f / (float)B;

    bucket_kernel<<<nsets, ATHREADS>>>(a1, a2);
    search_kernel<<<nblocksB, THREADS>>>(alpha, beta, out, nblocksB, scale);
}

// round 8
// speedup vs baseline: 3.6620x; 1.0411x over previous
#include <cuda_runtime.h>
#include <math.h>
#include <stdint.h>

// PointLoss_like_GPS — GB300 sm_103a, Round 8
// Fused single-kernel: bucketer blocks (2B) sort sets by x; searcher blocks
// (2B*32, 128 thr) spin on done-counter, stage sorted refs in dynamic smem,
// run warp-striped windowed NN scan (exact pruning) + ticketed reduction.

#define NPTS    4096
#define THREADS 128
#define NBUCK   64
#define XMIN    (-3.0f)
#define BW      (6.0f / NBUCK)       /* 3/32 exact; k*BW exact for k<=64 */
#define MAXSETS 8
#define SBPP    32                   /* searcher blocks per pair */
#define WPB     (THREADS / 32)       /* 4 warps per searcher block */

__device__ float        g_sx[MAXSETS][NPTS];
__device__ float        g_sy[MAXSETS][NPTS];
__device__ float        g_sz[MAXSETS][NPTS];
__device__ int          g_bstart[MAXSETS][NBUCK + 1];
__device__ float        g_partials[MAXSETS * SBPP];
__device__ unsigned int g_ticket;
__device__ unsigned int g_done;

__device__ __forceinline__ int bucket_of(float x)
{
    int b = (int)floorf((x - XMIN) * (1.0f / BW));
    return min(max(b, 0), NBUCK - 1);
}

__device__ __forceinline__ float2 addf32x2(unsigned long long a, unsigned long long b)
{
    float2 r;
    asm("{\n\t"
        ".reg .b64 t;\n\t"
        "add.rn.f32x2 t, %2, %3;\n\t"
        "mov.b64 {%0, %1}, t;\n\t"
        "}"
        : "=f"(r.x), "=f"(r.y) : "l"(a), "l"(b));
    return r;
}

__device__ __forceinline__ unsigned long long bcast2(float v)
{
    unsigned long long r;
    asm("mov.b64 %0, {%1, %1};" : "=l"(r) : "f"(v));
    return r;
}

// scan candidate groups [a,b) (4-aligned slop is idempotent for the min)
__device__ __forceinline__ void scan_range(
    const float* shX, const float* shY, const float* shZ,
    int a, int b,
    unsigned long long nqx2, unsigned long long nqy2, unsigned long long nqz2,
    float& dm0, float& dm1, float& dm2, float& dm3)
{
    const double2* X = (const double2*)shX;
    const double2* Y = (const double2*)shY;
    const double2* Z = (const double2*)shZ;
    const int g0 = a >> 2;
    const int g1 = (b + 3) >> 2;

    #pragma unroll 2
    for (int g = g0; g < g1; ++g) {
        const double2 xv = X[g], yv = Y[g], zv = Z[g];

        const float2 dx01 = addf32x2(__double_as_longlong(xv.x), nqx2);
        const float2 dx23 = addf32x2(__double_as_longlong(xv.y), nqx2);
        const float2 dy01 = addf32x2(__double_as_longlong(yv.x), nqy2);
        const float2 dy23 = addf32x2(__double_as_longlong(yv.y), nqy2);
        const float2 dz01 = addf32x2(__double_as_longlong(zv.x), nqz2);
        const float2 dz23 = addf32x2(__double_as_longlong(zv.y), nqz2);

        const float s0 = (fabsf(dx01.x) + fabsf(dy01.x)) + fabsf(dz01.x);
        const float s1 = (fabsf(dx01.y) + fabsf(dy01.y)) + fabsf(dz01.y);
        const float s2 = (fabsf(dx23.x) + fabsf(dy23.x)) + fabsf(dz23.x);
        const float s3 = (fabsf(dx23.y) + fabsf(dy23.y)) + fabsf(dz23.y);

        dm0 = fminf(dm0, s0);
        dm1 = fminf(dm1, s1);
        dm2 = fminf(dm2, s2);
        dm3 = fminf(dm3, s3);
    }
}

__global__ void __launch_bounds__(THREADS, 4)
gps_kernel(const float* __restrict__ a1,
           const float* __restrict__ a2,
           const float* __restrict__ alpha_p,
           const float* __restrict__ beta_p,
           float* __restrict__ out,
           int nsets, int nsearch, float scale)
{
    extern __shared__ __align__(16) float dyn[];   // 3*NPTS floats = 48 KB
    __shared__ float red[WPB];
    __shared__ unsigned int s_flag;

    const int tid = threadIdx.x;
    const int bx  = blockIdx.x;

    // ---------------- bucketer role ----------------
    if (bx < nsets) {
        int* hist = (int*)dyn;
        int* cur  = hist + NBUCK;

        const int s  = bx;
        const int bb = s >> 1;
        const float* base = ((s & 1) ? a2 : a1) + (size_t)bb * NPTS * 3;

        if (tid < NBUCK) hist[tid] = 0;
        __syncthreads();

        for (int i = tid; i < NPTS; i += THREADS)
            atomicAdd(&hist[bucket_of(base[i * 3])], 1);
        __syncthreads();

        if (tid == 0) {
            int acc = 0;
            for (int k = 0; k < NBUCK; k++) {
                cur[k] = acc;
                g_bstart[s][k] = acc;
                acc += hist[k];
            }
            g_bstart[s][NBUCK] = acc;
        }
        __syncthreads();

        for (int i = tid; i < NPTS; i += THREADS) {
            const float x = base[i * 3 + 0];
            const float y = base[i * 3 + 1];
            const float z = base[i * 3 + 2];
            const int pos = atomicAdd(&cur[bucket_of(x)], 1);
            g_sx[s][pos] = x;
            g_sy[s][pos] = y;
            g_sz[s][pos] = z;
        }
        __syncthreads();
        __threadfence();
        if (tid == 0) atomicAdd(&g_done, 1u);
        return;
    }

    // ---------------- searcher role ----------------
    const int sb = bx - nsets;           // [0, nsearch)
    const int p  = sb / SBPP;            // pair
    const int bl = sb % SBPP;
    const int bb = p >> 1;
    const int sset = (p & 1) ? (2 * bb) : (2 * bb + 1);
    const int rset = sset ^ 1;

    // wait for all bucketers (all blocks co-resident: 264 <= 4*152)
    if (tid == 0) {
        while (*((volatile unsigned int*)&g_done) < (unsigned)nsets)
            __nanosleep(64);
    }
    __syncthreads();
    __threadfence();

    float* shX = dyn;
    float* shY = dyn + NPTS;
    float* shZ = dyn + 2 * NPTS;
    {
        const float4* gx = (const float4*)g_sx[rset];
        const float4* gy = (const float4*)g_sy[rset];
        const float4* gz = (const float4*)g_sz[rset];
        #pragma unroll
        for (int i = 0; i < NPTS / 4 / THREADS; i++) {
            ((float4*)shX)[tid + i * THREADS] = gx[tid + i * THREADS];
            ((float4*)shY)[tid + i * THREADS] = gy[tid + i * THREADS];
            ((float4*)shZ)[tid + i * THREADS] = gz[tid + i * THREADS];
        }
    }
    __syncthreads();

    // warp striping: warp w handles sorted chunk  w*SBPP + bl
    const int w    = tid >> 5;
    const int lane = tid & 31;
    const int c    = w * SBPP + bl;      // [0, 128)
    const int q    = c * 32 + lane;      // sorted query index

    const float qx = g_sx[sset][q];
    const float qy = g_sy[sset][q];
    const float qz = g_sz[sset][q];

    const unsigned long long nqx2 = bcast2(-qx);
    const unsigned long long nqy2 = bcast2(-qy);
    const unsigned long long nqz2 = bcast2(-qz);

    const int* bst = g_bstart[rset];
    const int myb = bucket_of(qx);
    int blo = __shfl_sync(0xffffffffu, myb, 0);
    int bhi = __shfl_sync(0xffffffffu, myb, 31);

    float dm0 = 3.402823466e38f, dm1 = dm0, dm2 = dm0, dm3 = dm0;

    scan_range(shX, shY, shZ, __ldg(&bst[blo]), __ldg(&bst[bhi + 1]),
               nqx2, nqy2, nqz2, dm0, dm1, dm2, dm3);

    while (true) {
        const float dcur = fminf(fminf(dm0, dm1), fminf(dm2, dm3));
        const bool lok = (blo == 0) ||
                         (dcur <= qx - (XMIN + (float)blo * BW));
        const bool rok = (bhi == NBUCK - 1) ||
                         (dcur <= (XMIN + (float)(bhi + 1) * BW) - qx);
        if (__all_sync(0xffffffffu, lok && rok)) break;

        const int nlo = max(blo - 1, 0);
        const int nhi = min(bhi + 1, NBUCK - 1);
        if (nlo == blo && nhi == bhi) break;      // full coverage

        if (nlo < blo)
            scan_range(shX, shY, shZ, __ldg(&bst[nlo]), __ldg(&bst[blo]),
                       nqx2, nqy2, nqz2, dm0, dm1, dm2, dm3);
        if (nhi > bhi)
            scan_range(shX, shY, shZ, __ldg(&bst[bhi + 1]), __ldg(&bst[nhi + 1]),
                       nqx2, nqy2, nqz2, dm0, dm1, dm2, dm3);
        blo = nlo; bhi = nhi;
    }

    const float dmin = fminf(fminf(dm0, dm1), fminf(dm2, dm3));

    const float alpha = *alpha_p;
    const float beta  = *beta_p;
    const float delta = __powf(alpha, -1.0f / beta);
    const float sv = alpha * __powf(dmin, beta) + delta;
    float v = -sv * __expf(-sv);

    #pragma unroll
    for (int o = 16; o > 0; o >>= 1)
        v += __shfl_down_sync(0xffffffffu, v, o);
    if (lane == 0) red[w] = v;
    __syncthreads();

    if (tid == 0) {
        float bsum = 0.0f;
        #pragma unroll
        for (int k = 0; k < WPB; k++) bsum += red[k];
        g_partials[sb] = bsum;
        __threadfence();
        const unsigned int t = atomicAdd(&g_ticket, 1u);
        s_flag = (t == (unsigned)(nsearch - 1)) ? 1u : 0u;
    }
    __syncthreads();

    if (s_flag) {
        float acc = 0.0f;
        for (int i = tid; i < nsearch; i += THREADS)
            acc += *((volatile float*)&g_partials[i]);
        #pragma unroll
        for (int o = 16; o > 0; o >>= 1)
            acc += __shfl_down_sync(0xffffffffu, acc, o);
        if (lane == 0) red[w] = acc;
        __syncthreads();
        if (tid == 0) {
            out[0] = (red[0] + red[1] + red[2] + red[3]) * scale;
            g_ticket = 0;     // self-clean for graph replay
            g_done   = 0;
        }
    }
}

extern "C" void kernel_launch(void* const* d_in, const int* in_sizes, int n_in,
                              void* d_out, int out_size)
{
    const float* a1    = (const float*)d_in[0];
    const float* a2    = (const float*)d_in[1];
    const float* alpha = (const float*)d_in[2];
    const float* beta  = (const float*)d_in[3];
    float* out = (float*)d_out;

    const int B       = in_sizes[0] / (NPTS * 3);
    const int nsets   = 2 * B;               // 8
    const int nsearch = nsets * SBPP;        // 256
    const float scale = 50.0f / (float)B;

    const int smem = 3 * NPTS * (int)sizeof(float);   // 48 KB dynamic
    cudaFuncSetAttribute(gps_kernel,
                         cudaFuncAttributeMaxDynamicSharedMemorySize, smem);
    gps_kernel<<<nsets + nsearch, THREADS, smem>>>(a1, a2, alpha, beta, out,
                                                   nsets, nsearch, scale);
}